// round 10
// baseline (speedup 1.0000x reference)
#include <cuda_runtime.h>
#include <cuda_fp16.h>
#include <cstdint>

// ===========================================================================
// TensorTrainProjection via dense operator + single fp16 tensor-core GEMM.
//   W[d,j] = TT-contraction of 9 cores (2048 x 2048)
//   out = X @ W,  X: [8192, 2048] fp32
// fp16 GEMM (K=2048), W stored * 2^-8 (exact), epilogue * 256.
// Round-10: TWO launches total.
//   launch 0 (mega_pre): blocks 0..127 build W columns for one jh each
//     (full per-jh TT chain: cores 0-4 fixed-bottom fold + R from cores 5-8,
//      combine, fp16 quantize, pre-swizzled store). blocks 128..8319: conv_X.
//   launch 1: persistent fp16 GEMM (R8 version, plain stores - __stcs
//     regressed in R9 and is reverted).
// ===========================================================================

__device__ __forceinline__ uint32_t smem_u32(const void* p) {
    uint32_t a;
    asm("{ .reg .u64 t; cvta.to.shared.u64 t, %1; cvt.u32.u64 %0, t; }" : "=r"(a) : "l"(p));
    return a;
}
__device__ __forceinline__ uint32_t swz(uint32_t o) { return o ^ ((o >> 3) & 0x70); }

__device__ __forceinline__ uint32_t h2u(__half2 v) {
    return (uint32_t)__half_as_ushort(__low2half(v)) |
           ((uint32_t)__half_as_ushort(__high2half(v)) << 16);
}
__device__ __forceinline__ uint32_t pack2h(__half a, __half b) {
    return (uint32_t)__half_as_ushort(a) | ((uint32_t)__half_as_ushort(b) << 16);
}

__device__ __forceinline__ void cp16(uint32_t dst, const void* src) {
    asm volatile("cp.async.cg.shared.global [%0], [%1], 16;" :: "r"(dst), "l"(src) : "memory");
}
__device__ __forceinline__ void cp_commit() { asm volatile("cp.async.commit_group;" ::: "memory"); }
template <int N>
__device__ __forceinline__ void cp_wait() { asm volatile("cp.async.wait_group %0;" :: "n"(N) : "memory"); }

__device__ __forceinline__ void ldsm_x4(uint32_t* r, uint32_t addr) {
    asm volatile("ldmatrix.sync.aligned.m8n8.x4.shared.b16 {%0,%1,%2,%3}, [%4];"
                 : "=r"(r[0]), "=r"(r[1]), "=r"(r[2]), "=r"(r[3]) : "r"(addr));
}
__device__ __forceinline__ void mma16816f16(float* c, const uint32_t* a, const uint32_t* b) {
    asm volatile(
        "mma.sync.aligned.m16n8k16.row.col.f32.f16.f16.f32 "
        "{%0,%1,%2,%3}, {%4,%5,%6,%7}, {%8,%9}, {%0,%1,%2,%3};"
        : "+f"(c[0]), "+f"(c[1]), "+f"(c[2]), "+f"(c[3])
        : "r"(a[0]), "r"(a[1]), "r"(a[2]), "r"(a[3]), "r"(b[0]), "r"(b[1]));
}

// ---------------- scratch (static __device__, no allocs) --------------------
static __device__ __align__(16) unsigned char g_Xh[33554432];  // 64 mt * 32 ch * 16KB
static __device__ __align__(16) unsigned char g_Wh[8388608];   // 16 nt * 32 ch * 16KB

// ---------------- launch 0: fused pre ---------------------------------------
// blocks 0..127: build W for jh = blockIdx.x (16 j-columns, all 2048 d).
// blocks 128..8319: X -> fp16 pre-swizzled tiles.
__global__ void mega_pre(const float* __restrict__ x, unsigned char* __restrict__ Xh,
                         const float* __restrict__ p0, const float* __restrict__ p1,
                         const float* __restrict__ p2, const float* __restrict__ p3,
                         const float* __restrict__ p4, const float* __restrict__ p5,
                         const float* __restrict__ p6, const float* __restrict__ p7,
                         const float* __restrict__ p8, unsigned char* __restrict__ Wh)
{
    __shared__ float SA[4096], SB[4096], LsS[2048];
    int b = blockIdx.x, t = threadIdx.x;

    if (b >= 128) {
        // ---- conv_X (verified) ----
        int idx = (b - 128) * 256 + t;
        int m = idx >> 8;
        int k0 = (idx & 255) * 8;
        const float* row = x + (size_t)m * 2048 + k0;
        float4 v0 = *(const float4*)row;
        float4 v1 = *(const float4*)(row + 4);
        uint32_t off = (uint32_t)(((m >> 7) * 32 + (k0 >> 6)) << 14) + swz((m & 127) * 128 + (k0 & 63) * 2);
        uint4 pk;
        pk.x = h2u(__floats2half2_rn(v0.x, v0.y));
        pk.y = h2u(__floats2half2_rn(v0.z, v0.w));
        pk.z = h2u(__floats2half2_rn(v1.x, v1.y));
        pk.w = h2u(__floats2half2_rn(v1.z, v1.w));
        *(uint4*)(Xh + off) = pk;
        return;
    }

    // ================= W build for jh = b =================
    int jh = b;
    int j0 = jh >> 4;
    int b1 = (jh >> 3) & 1, b2 = (jh >> 2) & 1, b3 = (jh >> 1) & 1, b4 = jh & 1;

    // ---- phase 1: R from cores 8,7,6,5 (verified build_R logic) ----
    // X8 in SA[0..63], T7 in SB[0..255], S6 in SA[0..1023], R in SB[0..4095]
    if (t < 64) {
        int l = t >> 2, d = (t >> 1) & 1, jj = t & 1;
        SA[l * 4 + d * 2 + jj] = p8[(d * 2 + jj) * 16 + l];
    }
    __syncthreads();
    if (t < 256) {  // core 7: G[a,b,l,r] = p7[a][b][r][l] (swapped bonds)
        int l = t >> 4, dp = (t >> 2) & 3, jp = t & 3;
        int a = dp >> 1, d = dp & 1, bb = jp >> 1, jj = jp & 1;
        float acc = 0.f;
        #pragma unroll
        for (int r = 0; r < 16; ++r)
            acc = fmaf(p7[((a * 2 + bb) * 16 + r) * 16 + l], SA[r * 4 + d * 2 + jj], acc);
        SB[l * 16 + dp * 4 + jp] = acc;
    }
    __syncthreads();
    for (int i = t; i < 1024; i += 256) {  // core 6: SB(T7) -> SA(S6)
        int l = i >> 6, dp = (i >> 3) & 7, jp = i & 7;
        int a = dp >> 2, d = dp & 3, bb = jp >> 2, jj = jp & 3;
        float acc = 0.f;
        #pragma unroll
        for (int r = 0; r < 16; ++r)
            acc = fmaf(p6[((a * 2 + bb) * 16 + l) * 16 + r], SB[r * 16 + d * 4 + jj], acc);
        SA[l * 64 + dp * 8 + jp] = acc;
    }
    __syncthreads();
    for (int i = t; i < 4096; i += 256) {  // core 5: SA(S6) -> SB = R[l*256+dl*16+jl]
        int l = i >> 8, dp = (i >> 4) & 15, jp = i & 15;
        int a = dp >> 3, d = dp & 7, bb = jp >> 3, jj = jp & 7;
        float acc = 0.f;
        #pragma unroll
        for (int r = 0; r < 16; ++r)
            acc = fmaf(p5[((a * 2 + bb) * 16 + l) * 16 + r], SA[r * 64 + d * 8 + jj], acc);
        SB[i] = acc;
    }
    __syncthreads();

    // ---- phase 2: fixed-bottom chain cores 0..4 -> LsS[dh*16 + r] ----
    // A0[d0*16+l] at SA[0..127]
    if (t < 128) {
        int d0 = t >> 4, l = t & 15;
        SA[t] = p0[(d0 * 8 + j0) * 16 + l];
    }
    __syncthreads();
    if (t < 256) {  // A1[d1*16+r] at SA[512..767]
        int d1 = t >> 4, r = t & 15;
        int a = d1 & 1, d0 = d1 >> 1;
        float acc = 0.f;
        #pragma unroll
        for (int l = 0; l < 16; ++l)
            acc = fmaf(SA[d0 * 16 + l], p1[((a * 2 + b1) * 16 + l) * 16 + r], acc);
        SA[512 + t] = acc;
    }
    __syncthreads();
    for (int i = t; i < 512; i += 256) {  // A2[d2*16+r] at SA[1024..1535]
        int d2 = i >> 4, r = i & 15;
        int a = d2 & 1, d1 = d2 >> 1;
        float acc = 0.f;
        #pragma unroll
        for (int l = 0; l < 16; ++l)
            acc = fmaf(SA[512 + d1 * 16 + l], p2[((a * 2 + b2) * 16 + l) * 16 + r], acc);
        SA[1024 + i] = acc;
    }
    __syncthreads();
    for (int i = t; i < 1024; i += 256) {  // A3[d3*16+r] at SA[2048..3071]
        int d3 = i >> 4, r = i & 15;
        int a = d3 & 1, d2 = d3 >> 1;
        float acc = 0.f;
        #pragma unroll
        for (int l = 0; l < 16; ++l)
            acc = fmaf(SA[1024 + d2 * 16 + l], p3[((a * 2 + b3) * 16 + l) * 16 + r], acc);
        SA[2048 + i] = acc;
    }
    __syncthreads();
    for (int i = t; i < 2048; i += 256) {  // A4 = Ls[dh*16+r]
        int dh = i >> 4, r = i & 15;
        int a = dh & 1, d3 = dh >> 1;
        float acc = 0.f;
        #pragma unroll
        for (int l = 0; l < 16; ++l)
            acc = fmaf(SA[2048 + d3 * 16 + l], p4[((a * 2 + b4) * 16 + l) * 16 + r], acc);
        LsS[i] = acc;
    }
    __syncthreads();

    // ---- phase 3: combine + quantize + pre-swizzled store ----
    // thread t: jl = t>>4, d segment = (t&15)*128 .. +127 (16 uint4 writes)
    int jl = t >> 4;
    int dseg = (t & 15) * 128;
    int j = jh * 16 + jl;
    for (int q = 0; q < 16; ++q) {
        int d0b = dseg + q * 8;
        __half h[8];
        #pragma unroll
        for (int i = 0; i < 8; ++i) {
            int d = d0b + i;
            int dh = d >> 4, dl = d & 15;
            const float* lrow = LsS + dh * 16;
            float acc = 0.f;
            #pragma unroll
            for (int r = 0; r < 16; ++r)
                acc = fmaf(lrow[r], SB[r * 256 + dl * 16 + jl], acc);
            h[i] = __float2half_rn(acc * 0.00390625f);   // * 2^-8 exact
        }
        uint4 pk;
        pk.x = pack2h(h[0], h[1]);
        pk.y = pack2h(h[2], h[3]);
        pk.z = pack2h(h[4], h[5]);
        pk.w = pack2h(h[6], h[7]);
        uint32_t off = (uint32_t)(((j >> 7) * 32 + (d0b >> 6)) << 14)
                     + swz((j & 127) * 128 + (d0b & 63) * 2);
        *(uint4*)(Wh + off) = pk;
    }
}

// ---------------- launch 1: persistent fp16 GEMM (R8 version) ----------------
static constexpr int STAGE_BYTES = 32768;
static constexpr uint32_t GEMM_SMEM = 3 * STAGE_BYTES;

__global__ void __launch_bounds__(256, 2)
tt_gemm_f16(const unsigned char* __restrict__ Xh, const unsigned char* __restrict__ Wh,
            float* __restrict__ out)
{
    extern __shared__ unsigned char smem[];
    uint32_t sb = smem_u32(smem);
    int tid = threadIdx.x, wid = tid >> 5, lane = tid & 31;
    int cta = blockIdx.x;                          // 0..295
    int ntiles = (cta < 136) ? 4 : 3;              // 136*4 + 160*3 = 1024 tiles
    int total_it = ntiles << 5;                    // 32 k-chunks per tile

    int wm = (wid & 1) * 64;
    int wn = (wid >> 1) * 32;
    int arow = wm + (lane & 15);
    int akb  = (lane >> 4) * 16;
    int brow4 = wn + ((lane >> 4) & 1) * 8 + (lane & 7);
    int bkb   = ((lane >> 3) & 1) * 16;

    float acc[4][4][4];
    #pragma unroll
    for (int mi = 0; mi < 4; ++mi)
        #pragma unroll
        for (int ni = 0; ni < 4; ++ni)
            #pragma unroll
            for (int q = 0; q < 4; ++q) acc[mi][ni][q] = 0.f;

    auto issue = [&](int it2) {
        int ti = it2 >> 5, ck = it2 & 31;
        int tt = cta + 296 * ti;
        int by = tt >> 4, bx = tt & 15;
        const unsigned char* as = Xh + (((size_t)by * 32 + ck) << 14) + tid * 16;
        const unsigned char* bs = Wh + (((size_t)bx * 32 + ck) << 14) + tid * 16;
        uint32_t dst = sb + (uint32_t)(it2 % 3) * STAGE_BYTES + tid * 16;
        #pragma unroll
        for (int i = 0; i < 4; ++i) cp16(dst + i * 4096, as + i * 4096);
        #pragma unroll
        for (int i = 0; i < 4; ++i) cp16(dst + 16384 + i * 4096, bs + i * 4096);
    };

    issue(0); cp_commit();
    issue(1); cp_commit();

    for (int it = 0; it < total_it; ++it) {
        cp_wait<1>();
        __syncthreads();
        if (it + 2 < total_it) issue(it + 2);
        cp_commit();

        uint32_t base = sb + (uint32_t)(it % 3) * STAGE_BYTES;
        #pragma unroll
        for (int ks = 0; ks < 4; ++ks) {
            uint32_t af[4][4], bf[4][2];
            #pragma unroll
            for (int mi = 0; mi < 4; ++mi)
                ldsm_x4(af[mi], base + swz((uint32_t)((arow + mi * 16) * 128 + ks * 32 + akb)));
            #pragma unroll
            for (int blk = 0; blk < 2; ++blk) {
                uint32_t tmp[4];
                ldsm_x4(tmp, base + 16384 + swz((uint32_t)((brow4 + blk * 16) * 128 + ks * 32 + bkb)));
                bf[2 * blk][0] = tmp[0]; bf[2 * blk][1] = tmp[1];
                bf[2 * blk + 1][0] = tmp[2]; bf[2 * blk + 1][1] = tmp[3];
            }
            #pragma unroll
            for (int mi = 0; mi < 4; ++mi)
                #pragma unroll
                for (int ni = 0; ni < 4; ++ni)
                    mma16816f16(acc[mi][ni], af[mi], bf[ni]);
        }

        if ((it & 31) == 31) {
            int tt = cta + 296 * (it >> 5);
            int by = tt >> 4, bx = tt & 15;
            int m0 = by * 128 + wm + (lane >> 2);
            int n0 = bx * 128 + wn + (lane & 3) * 2;
            #pragma unroll
            for (int mi = 0; mi < 4; ++mi) {
                #pragma unroll
                for (int ni = 0; ni < 4; ++ni) {
                    float* pp = out + (size_t)(m0 + mi * 16) * 2048 + n0 + ni * 8;
                    *(float2*)pp = make_float2(acc[mi][ni][0] * 256.f, acc[mi][ni][1] * 256.f);
                    *(float2*)(pp + 8 * 2048) = make_float2(acc[mi][ni][2] * 256.f, acc[mi][ni][3] * 256.f);
                    #pragma unroll
                    for (int q = 0; q < 4; ++q) acc[mi][ni][q] = 0.f;
                }
            }
        }
    }
}

// ---------------- launch ------------------------------------------------------
extern "C" void kernel_launch(void* const* d_in, const int* in_sizes, int n_in,
                              void* d_out, int out_size)
{
    (void)in_sizes; (void)n_in; (void)out_size;
    const float* x = (const float*)d_in[0];
    const float* p[9];
    for (int i = 0; i < 9; ++i) p[i] = (const float*)d_in[1 + i];

    unsigned char *Xh, *Wh;
    cudaGetSymbolAddress((void**)&Xh, g_Xh);
    cudaGetSymbolAddress((void**)&Wh, g_Wh);

    mega_pre<<<8320, 256>>>(x, Xh, p[0], p[1], p[2], p[3], p[4],
                            p[5], p[6], p[7], p[8], Wh);                 // 0
    cudaFuncSetAttribute(tt_gemm_f16, cudaFuncAttributeMaxDynamicSharedMemorySize, GEMM_SMEM);
    tt_gemm_f16<<<296, 256, GEMM_SMEM>>>(Xh, Wh, (float*)d_out);         // 1
}

// round 11
// speedup vs baseline: 1.4458x; 1.4458x over previous
#include <cuda_runtime.h>
#include <cuda_fp16.h>
#include <cstdint>

// ===========================================================================
// TensorTrainProjection via dense operator + single fp16 tensor-core GEMM.
//   W[d,j] = TT-contraction of 9 cores (2048 x 2048)
//   out = X @ W,  X: [8192, 2048] fp32
// fp16 GEMM (K=2048), W stored * 2^-8 (exact), epilogue * 256.
// Round-11: best measured combination:
//   - R8 pre-work (5 lean kernels, ~47us total)
//   - R7 non-persistent GEMM (grid 1024, 3-stage cp.async, 158us measured;
//     persistence measured SLOWER at 182.5us in R9/R10 and is dropped)
// ===========================================================================

__device__ __forceinline__ uint32_t smem_u32(const void* p) {
    uint32_t a;
    asm("{ .reg .u64 t; cvta.to.shared.u64 t, %1; cvt.u32.u64 %0, t; }" : "=r"(a) : "l"(p));
    return a;
}
__device__ __forceinline__ uint32_t swz(uint32_t o) { return o ^ ((o >> 3) & 0x70); }

__device__ __forceinline__ uint32_t h2u(__half2 v) {
    return (uint32_t)__half_as_ushort(__low2half(v)) |
           ((uint32_t)__half_as_ushort(__high2half(v)) << 16);
}
__device__ __forceinline__ uint32_t pack2h(__half a, __half b) {
    return (uint32_t)__half_as_ushort(a) | ((uint32_t)__half_as_ushort(b) << 16);
}

__device__ __forceinline__ void cp16(uint32_t dst, const void* src) {
    asm volatile("cp.async.cg.shared.global [%0], [%1], 16;" :: "r"(dst), "l"(src) : "memory");
}
__device__ __forceinline__ void cp_commit() { asm volatile("cp.async.commit_group;" ::: "memory"); }
template <int N>
__device__ __forceinline__ void cp_wait() { asm volatile("cp.async.wait_group %0;" :: "n"(N) : "memory"); }

__device__ __forceinline__ void ldsm_x4(uint32_t* r, uint32_t addr) {
    asm volatile("ldmatrix.sync.aligned.m8n8.x4.shared.b16 {%0,%1,%2,%3}, [%4];"
                 : "=r"(r[0]), "=r"(r[1]), "=r"(r[2]), "=r"(r[3]) : "r"(addr));
}
__device__ __forceinline__ void ldsm_x2(uint32_t* r, uint32_t addr) {
    asm volatile("ldmatrix.sync.aligned.m8n8.x2.shared.b16 {%0,%1}, [%2];"
                 : "=r"(r[0]), "=r"(r[1]) : "r"(addr));
}
__device__ __forceinline__ void mma16816f16(float* c, const uint32_t* a, const uint32_t* b) {
    asm volatile(
        "mma.sync.aligned.m16n8k16.row.col.f32.f16.f16.f32 "
        "{%0,%1,%2,%3}, {%4,%5,%6,%7}, {%8,%9}, {%0,%1,%2,%3};"
        : "+f"(c[0]), "+f"(c[1]), "+f"(c[2]), "+f"(c[3])
        : "r"(a[0]), "r"(a[1]), "r"(a[2]), "r"(a[3]), "r"(b[0]), "r"(b[1]));
}

// ---------------- scratch (static __device__, no allocs) --------------------
static __device__ __align__(16) unsigned char g_Xh[33554432];  // 64 mt * 32 ch * 16KB
static __device__ __align__(16) unsigned char g_Wh[8388608];   // 16 nt * 32 ch * 16KB
static __device__ float g_S2[16384];                           // [32][32][16]
static __device__ float g_R[4096];                             // [16][16][16]
static __device__ float g_Ls[262144];                          // [128 jh][2048]

// ---------------- launch 0: X -> fp16 pre-swizzled tiles --------------------
__global__ void conv_X(const float* __restrict__ x, unsigned char* __restrict__ Xh)
{
    int idx = blockIdx.x * blockDim.x + threadIdx.x;   // < 8192*256
    int m = idx >> 8;
    int k0 = (idx & 255) * 8;
    const float* row = x + (size_t)m * 2048 + k0;
    float4 v0 = *(const float4*)row;
    float4 v1 = *(const float4*)(row + 4);
    uint32_t off = (uint32_t)(((m >> 7) * 32 + (k0 >> 6)) << 14) + swz((m & 127) * 128 + (k0 & 63) * 2);
    uint4 pk;
    pk.x = h2u(__floats2half2_rn(v0.x, v0.y));
    pk.y = h2u(__floats2half2_rn(v0.z, v0.w));
    pk.z = h2u(__floats2half2_rn(v1.x, v1.y));
    pk.w = h2u(__floats2half2_rn(v1.z, v1.w));
    *(uint4*)(Xh + off) = pk;
}

// ---------------- launch 1: cores 0-2 -> S2[32][32][16] (verified) -----------
__global__ void tt_chain12(const float* __restrict__ p0, const float* __restrict__ p1,
                           const float* __restrict__ p2, float* __restrict__ out)
{
    __shared__ float s0[1024];
    __shared__ float s1[4096];
    __shared__ float c[1024];
    int t = threadIdx.x;
    for (int i = t; i < 1024; i += 256) { s0[i] = p0[i]; c[i] = p1[i]; }
    __syncthreads();
    for (int idx = t; idx < 256; idx += 256) {
        int b = idx & 1, j = (idx >> 1) & 7, a = (idx >> 4) & 1, d = idx >> 5;
        const float* sr = s0 + (d * 8 + j) * 16;
        int ab = a * 2 + b;
        float* o = s1 + ((d * 2 + a) * 16 + (j * 2 + b)) * 16;
        #pragma unroll
        for (int r = 0; r < 16; ++r) {
            float acc = 0.f;
            #pragma unroll
            for (int l = 0; l < 16; ++l) acc = fmaf(sr[l], c[(ab * 16 + l) * 16 + r], acc);
            o[r] = acc;
        }
    }
    __syncthreads();
    for (int i = t; i < 1024; i += 256) c[i] = p2[i];
    __syncthreads();
    for (int idx = t; idx < 1024; idx += 256) {
        int b = idx & 1, j = (idx >> 1) & 15, a = (idx >> 5) & 1, d = idx >> 6;
        const float* sr = s1 + (d * 16 + j) * 16;
        int ab = a * 2 + b;
        float* o = out + ((d * 2 + a) * 32 + (j * 2 + b)) * 16;
        #pragma unroll
        for (int r = 0; r < 16; ++r) {
            float acc = 0.f;
            #pragma unroll
            for (int l = 0; l < 16; ++l) acc = fmaf(sr[l], c[(ab * 16 + l) * 16 + r], acc);
            o[r] = acc;
        }
    }
}

// ---------------- launch 2: R = cores 8,7,6,5 (verified) ---------------------
__global__ void build_R(const float* __restrict__ p5, const float* __restrict__ p6,
                        const float* __restrict__ p7, const float* __restrict__ p8,
                        float* __restrict__ Rout)
{
    __shared__ float S[4096], T[4096];
    int t = threadIdx.x;
    if (t < 64) { int l = t >> 2, d = (t >> 1) & 1, jj = t & 1; S[l * 4 + d * 2 + jj] = p8[(d * 2 + jj) * 16 + l]; }
    __syncthreads();
    if (t < 256) {  // core 7: G[a,b,l,r] = p7[a][b][r][l] (swapped bonds)
        int l = t >> 4, dp = (t >> 2) & 3, jp = t & 3;
        int a = dp >> 1, d = dp & 1, b = jp >> 1, jj = jp & 1;
        float acc = 0.f;
        #pragma unroll
        for (int r = 0; r < 16; ++r) acc = fmaf(p7[((a * 2 + b) * 16 + r) * 16 + l], S[r * 4 + d * 2 + jj], acc);
        T[l * 16 + dp * 4 + jp] = acc;
    }
    __syncthreads();
    for (int i = t; i < 1024; i += 256) {  // core 6
        int l = i >> 6, dp = (i >> 3) & 7, jp = i & 7;
        int a = dp >> 2, d = dp & 3, b = jp >> 2, jj = jp & 3;
        float acc = 0.f;
        #pragma unroll
        for (int r = 0; r < 16; ++r) acc = fmaf(p6[((a * 2 + b) * 16 + l) * 16 + r], T[r * 16 + d * 4 + jj], acc);
        S[l * 64 + dp * 8 + jp] = acc;
    }
    __syncthreads();
    for (int i = t; i < 4096; i += 256) {  // core 5 -> R[l*256 + dl*16 + jl]
        int l = i >> 8, dp = (i >> 4) & 15, jp = i & 15;
        int a = dp >> 3, d = dp & 7, b = jp >> 3, jj = jp & 7;
        float acc = 0.f;
        #pragma unroll
        for (int r = 0; r < 16; ++r) acc = fmaf(p5[((a * 2 + b) * 16 + l) * 16 + r], S[r * 64 + d * 8 + jj], acc);
        Rout[i] = acc;
    }
}

// ---------------- launch 3: Ls[jh][dh*16+r] via cores 3,4 (128 blocks) -------
__global__ void build_Ls(const float* __restrict__ S2,
                         const float* __restrict__ p3, const float* __restrict__ p4,
                         float* __restrict__ Lsg)
{
    __shared__ float S[3584];
    int t = threadIdx.x, jh = blockIdx.x;
    for (int i = t; i < 512; i += 256) {
        int d2 = i >> 4, l = i & 15;
        S[i] = S2[((d2 * 32) + (jh >> 2)) * 16 + l];
    }
    for (int i = t; i < 1024; i += 256) { S[512 + i] = p3[i]; S[2560 + i] = p4[i]; }
    __syncthreads();
    for (int i = t; i < 1024; i += 256) {   // core 3: T3[d3*16+r]
        int d3 = i >> 4, r = i & 15;
        int a = d3 & 1, b3 = (jh >> 1) & 1, d2 = d3 >> 1;
        float acc = 0.f;
        #pragma unroll
        for (int l = 0; l < 16; ++l)
            acc = fmaf(S[d2 * 16 + l], S[512 + ((a * 2 + b3) * 16 + l) * 16 + r], acc);
        S[1536 + i] = acc;
    }
    __syncthreads();
    float* o = Lsg + (size_t)jh * 2048;
    for (int i = t; i < 2048; i += 256) {   // core 4: Ls[dh*16+r]
        int dh = i >> 4, r = i & 15;
        int a = dh & 1, b4 = jh & 1, d3 = dh >> 1;
        float acc = 0.f;
        #pragma unroll
        for (int l = 0; l < 16; ++l)
            acc = fmaf(S[1536 + d3 * 16 + l], S[2560 + ((a * 2 + b4) * 16 + l) * 16 + r], acc);
        o[i] = acc;
    }
}

// ---------------- launch 4: combine -> Wh (fp16 * 2^-8, pre-swizzled) --------
__global__ void combine_W(const float* __restrict__ Lsg, const float* __restrict__ Rg,
                          unsigned char* __restrict__ Wh)
{
    __shared__ float ls[2048], rr[256];
    int t = threadIdx.x, j = blockIdx.x;
    int jh = j >> 4, jl = j & 15;
    const float* lsrc = Lsg + (size_t)jh * 2048;
    for (int i = t; i < 2048; i += 256) ls[i] = lsrc[i];
    { int r = t >> 4, dl = t & 15; rr[t] = Rg[r * 256 + dl * 16 + jl]; }
    __syncthreads();

    __half h[8];
    int dh = t >> 1;
    const float* lrow = ls + dh * 16;
    #pragma unroll
    for (int i = 0; i < 8; ++i) {
        int dl = (t & 1) * 8 + i;
        float acc = 0.f;
        #pragma unroll
        for (int r = 0; r < 16; ++r)
            acc = fmaf(lrow[r], rr[r * 16 + dl], acc);
        h[i] = __float2half_rn(acc * 0.00390625f);   // * 2^-8 exact
    }
    uint4 pk;
    pk.x = pack2h(h[0], h[1]);
    pk.y = pack2h(h[2], h[3]);
    pk.z = pack2h(h[4], h[5]);
    pk.w = pack2h(h[6], h[7]);
    uint32_t off = (uint32_t)(((j >> 7) * 32 + ((t * 8) >> 6)) << 14) + swz((j & 127) * 128 + ((t * 8) & 63) * 2);
    *(uint4*)(Wh + off) = pk;
}

// ---------------- launch 5: fp16 GEMM (R7 version, non-persistent) -----------
// CTA 128x128, 32 K-chunks of 64, 3-stage cp.async pipeline.
// 8 warps (2m x 4n), warp tile 64x32. Epilogue scales by 256 (W was * 2^-8).
static constexpr int GSTAGES = 3;
static constexpr int STAGE_BYTES = 32768;
static constexpr uint32_t GEMM_SMEM = GSTAGES * STAGE_BYTES;

__device__ __forceinline__ void issue_stage(uint32_t sb, int buf, int ck, int tid,
                                            const unsigned char* __restrict__ Xh,
                                            const unsigned char* __restrict__ Wh,
                                            int by, int bx)
{
    const unsigned char* as = Xh + (((size_t)by * 32 + ck) << 14) + tid * 16;
    const unsigned char* bs = Wh + (((size_t)bx * 32 + ck) << 14) + tid * 16;
    uint32_t dst = sb + buf * STAGE_BYTES + tid * 16;
    #pragma unroll
    for (int i = 0; i < 4; ++i) cp16(dst + i * 4096, as + i * 4096);
    #pragma unroll
    for (int i = 0; i < 4; ++i) cp16(dst + 16384 + i * 4096, bs + i * 4096);
}

__global__ void __launch_bounds__(256, 2)
tt_gemm_f16(const unsigned char* __restrict__ Xh, const unsigned char* __restrict__ Wh,
            float* __restrict__ out)
{
    extern __shared__ unsigned char smem[];
    uint32_t sb = smem_u32(smem);
    int tid = threadIdx.x, wid = tid >> 5, lane = tid & 31;
    int bx = blockIdx.x, by = blockIdx.y;

    int wm = (wid & 1) * 64;
    int wn = (wid >> 1) * 32;
    int arow = wm + (lane & 15);
    int akb  = (lane >> 4) * 16;
    int brow = wn + (lane & 7);
    int bkb  = ((lane >> 3) & 1) * 16;

    float acc[4][4][4];
    #pragma unroll
    for (int mi = 0; mi < 4; ++mi)
        #pragma unroll
        for (int ni = 0; ni < 4; ++ni)
            #pragma unroll
            for (int q = 0; q < 4; ++q) acc[mi][ni][q] = 0.f;

    #pragma unroll
    for (int s = 0; s < GSTAGES - 1; ++s) {
        issue_stage(sb, s, s, tid, Xh, Wh, by, bx);
        cp_commit();
    }

    for (int it = 0; it < 32; ++it) {
        cp_wait<GSTAGES - 2>();
        __syncthreads();

        int nxt = it + GSTAGES - 1;
        if (nxt < 32) issue_stage(sb, nxt % GSTAGES, nxt, tid, Xh, Wh, by, bx);
        cp_commit();

        uint32_t base = sb + (it % GSTAGES) * STAGE_BYTES;
        #pragma unroll
        for (int ks = 0; ks < 4; ++ks) {
            uint32_t af[4][4], bf[4][2];
            #pragma unroll
            for (int mi = 0; mi < 4; ++mi)
                ldsm_x4(af[mi], base + swz((uint32_t)((arow + mi * 16) * 128 + ks * 32 + akb)));
            #pragma unroll
            for (int ni = 0; ni < 4; ++ni)
                ldsm_x2(bf[ni], base + 16384 + swz((uint32_t)((brow + ni * 8) * 128 + ks * 32 + bkb)));
            #pragma unroll
            for (int mi = 0; mi < 4; ++mi)
                #pragma unroll
                for (int ni = 0; ni < 4; ++ni)
                    mma16816f16(acc[mi][ni], af[mi], bf[ni]);
        }
    }

    int m0 = by * 128 + wm + (lane >> 2);
    int n0 = bx * 128 + wn + (lane & 3) * 2;
    #pragma unroll
    for (int mi = 0; mi < 4; ++mi) {
        #pragma unroll
        for (int ni = 0; ni < 4; ++ni) {
            float* p = out + (size_t)(m0 + mi * 16) * 2048 + n0 + ni * 8;
            *(float2*)p = make_float2(acc[mi][ni][0] * 256.f, acc[mi][ni][1] * 256.f);
            *(float2*)(p + 8 * 2048) = make_float2(acc[mi][ni][2] * 256.f, acc[mi][ni][3] * 256.f);
        }
    }
}

// ---------------- launch ------------------------------------------------------
extern "C" void kernel_launch(void* const* d_in, const int* in_sizes, int n_in,
                              void* d_out, int out_size)
{
    (void)in_sizes; (void)n_in; (void)out_size;
    const float* x = (const float*)d_in[0];
    const float* p[9];
    for (int i = 0; i < 9; ++i) p[i] = (const float*)d_in[1 + i];

    unsigned char *Xh, *Wh;
    float *S2, *R, *Ls;
    cudaGetSymbolAddress((void**)&Xh, g_Xh);
    cudaGetSymbolAddress((void**)&Wh, g_Wh);
    cudaGetSymbolAddress((void**)&S2, g_S2);
    cudaGetSymbolAddress((void**)&R, g_R);
    cudaGetSymbolAddress((void**)&Ls, g_Ls);

    conv_X<<<8192, 256>>>(x, Xh);                                  // 0
    tt_chain12<<<1, 256>>>(p[0], p[1], p[2], S2);                  // 1
    build_R<<<1, 256>>>(p[5], p[6], p[7], p[8], R);                // 2
    build_Ls<<<128, 256>>>(S2, p[3], p[4], Ls);                    // 3
    combine_W<<<2048, 256>>>(Ls, R, Wh);                           // 4
    cudaFuncSetAttribute(tt_gemm_f16, cudaFuncAttributeMaxDynamicSharedMemorySize, GEMM_SMEM);
    tt_gemm_f16<<<dim3(16, 64), 256, GEMM_SMEM>>>(Xh, Wh, (float*)d_out);  // 5
}

// round 12
// speedup vs baseline: 1.5091x; 1.0438x over previous
#include <cuda_runtime.h>
#include <cuda_fp16.h>
#include <cstdint>

// ===========================================================================
// TensorTrainProjection via dense operator + single fp16 tensor-core GEMM.
//   W[d,j] = TT-contraction of 9 cores (2048 x 2048)
//   out = X @ W,  X: [8192, 2048] fp32
// fp16 GEMM (K=2048), W stored * 2^-8 (exact), epilogue * 256.
// Round-12: THREE launches.
//   0: conv_X (8192 blocks)  - X -> fp16 pre-swizzled tiles
//   1: W_all  (128 blocks)   - per-jh: chain12-slice + R + Ls + combine+quant
//      (per-block R/chain recompute costs ~0.6us chip-wide; kills 3 launches
//       and all W gmem roundtrips. Ls stored transposed [r][dh] to kill the
//       16-way smem bank conflict that sank R10.)
//   2: GEMM - R7/R11 kernel verbatim (measured best, 158us).
// All inner-loop summation orders preserved -> W bit-identical to R11
// (rel_err must stay exactly 2.934e-4; deviation = indexing bug).
// ===========================================================================

__device__ __forceinline__ uint32_t smem_u32(const void* p) {
    uint32_t a;
    asm("{ .reg .u64 t; cvta.to.shared.u64 t, %1; cvt.u32.u64 %0, t; }" : "=r"(a) : "l"(p));
    return a;
}
__device__ __forceinline__ uint32_t swz(uint32_t o) { return o ^ ((o >> 3) & 0x70); }

__device__ __forceinline__ uint32_t h2u(__half2 v) {
    return (uint32_t)__half_as_ushort(__low2half(v)) |
           ((uint32_t)__half_as_ushort(__high2half(v)) << 16);
}
__device__ __forceinline__ uint32_t pack2h(__half a, __half b) {
    return (uint32_t)__half_as_ushort(a) | ((uint32_t)__half_as_ushort(b) << 16);
}

__device__ __forceinline__ void cp16(uint32_t dst, const void* src) {
    asm volatile("cp.async.cg.shared.global [%0], [%1], 16;" :: "r"(dst), "l"(src) : "memory");
}
__device__ __forceinline__ void cp_commit() { asm volatile("cp.async.commit_group;" ::: "memory"); }
template <int N>
__device__ __forceinline__ void cp_wait() { asm volatile("cp.async.wait_group %0;" :: "n"(N) : "memory"); }

__device__ __forceinline__ void ldsm_x4(uint32_t* r, uint32_t addr) {
    asm volatile("ldmatrix.sync.aligned.m8n8.x4.shared.b16 {%0,%1,%2,%3}, [%4];"
                 : "=r"(r[0]), "=r"(r[1]), "=r"(r[2]), "=r"(r[3]) : "r"(addr));
}
__device__ __forceinline__ void ldsm_x2(uint32_t* r, uint32_t addr) {
    asm volatile("ldmatrix.sync.aligned.m8n8.x2.shared.b16 {%0,%1}, [%2];"
                 : "=r"(r[0]), "=r"(r[1]) : "r"(addr));
}
__device__ __forceinline__ void mma16816f16(float* c, const uint32_t* a, const uint32_t* b) {
    asm volatile(
        "mma.sync.aligned.m16n8k16.row.col.f32.f16.f16.f32 "
        "{%0,%1,%2,%3}, {%4,%5,%6,%7}, {%8,%9}, {%0,%1,%2,%3};"
        : "+f"(c[0]), "+f"(c[1]), "+f"(c[2]), "+f"(c[3])
        : "r"(a[0]), "r"(a[1]), "r"(a[2]), "r"(a[3]), "r"(b[0]), "r"(b[1]));
}

// ---------------- scratch (static __device__, no allocs) --------------------
static __device__ __align__(16) unsigned char g_Xh[33554432];  // 64 mt * 32 ch * 16KB
static __device__ __align__(16) unsigned char g_Wh[8388608];   // 16 nt * 32 ch * 16KB

// ---------------- launch 0: X -> fp16 pre-swizzled tiles (verified) ----------
__global__ void conv_X(const float* __restrict__ x, unsigned char* __restrict__ Xh)
{
    int idx = blockIdx.x * blockDim.x + threadIdx.x;   // < 8192*256
    int m = idx >> 8;
    int k0 = (idx & 255) * 8;
    const float* row = x + (size_t)m * 2048 + k0;
    float4 v0 = *(const float4*)row;
    float4 v1 = *(const float4*)(row + 4);
    uint32_t off = (uint32_t)(((m >> 7) * 32 + (k0 >> 6)) << 14) + swz((m & 127) * 128 + (k0 & 63) * 2);
    uint4 pk;
    pk.x = h2u(__floats2half2_rn(v0.x, v0.y));
    pk.y = h2u(__floats2half2_rn(v0.z, v0.w));
    pk.z = h2u(__floats2half2_rn(v1.x, v1.y));
    pk.w = h2u(__floats2half2_rn(v1.z, v1.w));
    *(uint4*)(Xh + off) = pk;
}

// ---------------- launch 1: W_all (grid 128, one jh per block) ---------------
// BUF float regions: R0 = [0..4095] (S2slice temp, then R final)
//                    SC = [4096..10239] (scratch: chain s0/c/s1, p3/p4/T3, R S)
//                    LS = [10240..12287] (Ls transposed: LS[r*128 + dh])
__global__ void W_all(const float* __restrict__ p0, const float* __restrict__ p1,
                      const float* __restrict__ p2, const float* __restrict__ p3,
                      const float* __restrict__ p4, const float* __restrict__ p5,
                      const float* __restrict__ p6, const float* __restrict__ p7,
                      const float* __restrict__ p8, unsigned char* __restrict__ Wh)
{
    __shared__ float BUF[12288];
    float* R0 = BUF;
    float* SC = BUF + 4096;
    float* LS = BUF + 10240;
    int t = threadIdx.x, jh = blockIdx.x;
    int j2 = jh >> 2;

    // ---- phase A: cores 0-2, only column j2 (verified chain12 math) ----
    {
        float* s0 = SC;           // 1024
        float* cc = SC + 1024;    // 1024
        float* s1 = SC + 2048;    // 4096
        for (int i = t; i < 1024; i += 256) { s0[i] = p0[i]; cc[i] = p1[i]; }
        __syncthreads();
        {   // step 1 (full, 256 outputs x 16r)
            int idx = t;
            int b = idx & 1, j = (idx >> 1) & 7, a = (idx >> 4) & 1, d = idx >> 5;
            const float* sr = s0 + (d * 8 + j) * 16;
            int ab = a * 2 + b;
            float* o = s1 + ((d * 2 + a) * 16 + (j * 2 + b)) * 16;
            #pragma unroll
            for (int r = 0; r < 16; ++r) {
                float acc = 0.f;
                #pragma unroll
                for (int l = 0; l < 16; ++l) acc = fmaf(sr[l], cc[(ab * 16 + l) * 16 + r], acc);
                o[r] = acc;
            }
        }
        __syncthreads();
        for (int i = t; i < 1024; i += 256) cc[i] = p2[i];
        __syncthreads();
        {   // step 2, only output column j2: S2slice[d2o*16 + r] -> R0[0..511]
            int jj = j2 >> 1, bb = j2 & 1;
            for (int i = t; i < 512; i += 256) {
                int d2o = i >> 4, r = i & 15;
                int d = d2o >> 1, a = d2o & 1;
                const float* sr = s1 + (d * 16 + jj) * 16;
                int ab = a * 2 + bb;
                float acc = 0.f;
                #pragma unroll
                for (int l = 0; l < 16; ++l) acc = fmaf(sr[l], cc[(ab * 16 + l) * 16 + r], acc);
                R0[i] = acc;
            }
        }
    }
    __syncthreads();

    // ---- phase B: cores 3,4 -> LS[r*128 + dh] (transposed, conflict-free D) ----
    {
        for (int i = t; i < 1024; i += 256) { SC[i] = p3[i]; SC[1024 + i] = p4[i]; }
        __syncthreads();
        float* T3 = SC + 2048;     // 1024 (overwrites dead s1)
        int b3 = (jh >> 1) & 1, b4 = jh & 1;
        for (int i = t; i < 1024; i += 256) {   // core 3
            int d3 = i >> 4, r = i & 15;
            int a = d3 & 1, d2 = d3 >> 1;
            float acc = 0.f;
            #pragma unroll
            for (int l = 0; l < 16; ++l)
                acc = fmaf(R0[d2 * 16 + l], SC[((a * 2 + b3) * 16 + l) * 16 + r], acc);
            T3[i] = acc;
        }
        __syncthreads();
        for (int i = t; i < 2048; i += 256) {   // core 4, transposed store
            int dh = i & 127, r = i >> 7;
            int a = dh & 1, d3 = dh >> 1;
            float acc = 0.f;
            #pragma unroll
            for (int l = 0; l < 16; ++l)
                acc = fmaf(T3[d3 * 16 + l], SC[1024 + ((a * 2 + b4) * 16 + l) * 16 + r], acc);
            LS[i] = acc;    // LS[r*128 + dh]
        }
    }
    __syncthreads();

    // ---- phase C: R from cores 8,7,6,5 (verified build_R; S=SC, T=R0) ----
    {
        float* S = SC;
        float* T = R0;
        if (t < 64) { int l = t >> 2, d = (t >> 1) & 1, jj = t & 1; S[l * 4 + d * 2 + jj] = p8[(d * 2 + jj) * 16 + l]; }
        __syncthreads();
        if (t < 256) {  // core 7: G[a,b,l,r] = p7[a][b][r][l] (swapped bonds)
            int l = t >> 4, dp = (t >> 2) & 3, jp = t & 3;
            int a = dp >> 1, d = dp & 1, bb = jp >> 1, jj = jp & 1;
            float acc = 0.f;
            #pragma unroll
            for (int r = 0; r < 16; ++r) acc = fmaf(p7[((a * 2 + bb) * 16 + r) * 16 + l], S[r * 4 + d * 2 + jj], acc);
            T[l * 16 + dp * 4 + jp] = acc;
        }
        __syncthreads();
        for (int i = t; i < 1024; i += 256) {  // core 6
            int l = i >> 6, dp = (i >> 3) & 7, jp = i & 7;
            int a = dp >> 2, d = dp & 3, bb = jp >> 2, jj = jp & 3;
            float acc = 0.f;
            #pragma unroll
            for (int r = 0; r < 16; ++r) acc = fmaf(p6[((a * 2 + bb) * 16 + l) * 16 + r], T[r * 16 + d * 4 + jj], acc);
            S[l * 64 + dp * 8 + jp] = acc;
        }
        __syncthreads();
        for (int i = t; i < 4096; i += 256) {  // core 5 -> R0[l*256 + dl*16 + jl]
            int l = i >> 8, dp = (i >> 4) & 15, jp = i & 15;
            int a = dp >> 3, d = dp & 7, bb = jp >> 3, jj = jp & 7;
            float acc = 0.f;
            #pragma unroll
            for (int r = 0; r < 16; ++r) acc = fmaf(p5[((a * 2 + bb) * 16 + l) * 16 + r], S[r * 64 + d * 8 + jj], acc);
            T[i] = acc;
        }
    }
    __syncthreads();

    // ---- phase D: combine + quantize + pre-swizzled store (16 columns) ----
    int dh = t >> 1;
    for (int jl = 0; jl < 16; ++jl) {
        int j = jh * 16 + jl;
        __half h[8];
        #pragma unroll
        for (int i = 0; i < 8; ++i) {
            int dl = (t & 1) * 8 + i;
            float acc = 0.f;
            #pragma unroll
            for (int r = 0; r < 16; ++r)
                acc = fmaf(LS[r * 128 + dh], R0[r * 256 + dl * 16 + jl], acc);
            h[i] = __float2half_rn(acc * 0.00390625f);   // * 2^-8 exact
        }
        uint4 pk;
        pk.x = pack2h(h[0], h[1]);
        pk.y = pack2h(h[2], h[3]);
        pk.z = pack2h(h[4], h[5]);
        pk.w = pack2h(h[6], h[7]);
        uint32_t off = (uint32_t)(((j >> 7) * 32 + ((t * 8) >> 6)) << 14)
                     + swz((j & 127) * 128 + ((t * 8) & 63) * 2);
        *(uint4*)(Wh + off) = pk;
    }
}

// ---------------- launch 2: fp16 GEMM (R7/R11 version, measured best) --------
static constexpr int GSTAGES = 3;
static constexpr int STAGE_BYTES = 32768;
static constexpr uint32_t GEMM_SMEM = GSTAGES * STAGE_BYTES;

__device__ __forceinline__ void issue_stage(uint32_t sb, int buf, int ck, int tid,
                                            const unsigned char* __restrict__ Xh,
                                            const unsigned char* __restrict__ Wh,
                                            int by, int bx)
{
    const unsigned char* as = Xh + (((size_t)by * 32 + ck) << 14) + tid * 16;
    const unsigned char* bs = Wh + (((size_t)bx * 32 + ck) << 14) + tid * 16;
    uint32_t dst = sb + buf * STAGE_BYTES + tid * 16;
    #pragma unroll
    for (int i = 0; i < 4; ++i) cp16(dst + i * 4096, as + i * 4096);
    #pragma unroll
    for (int i = 0; i < 4; ++i) cp16(dst + 16384 + i * 4096, bs + i * 4096);
}

__global__ void __launch_bounds__(256, 2)
tt_gemm_f16(const unsigned char* __restrict__ Xh, const unsigned char* __restrict__ Wh,
            float* __restrict__ out)
{
    extern __shared__ unsigned char smem[];
    uint32_t sb = smem_u32(smem);
    int tid = threadIdx.x, wid = tid >> 5, lane = tid & 31;
    int bx = blockIdx.x, by = blockIdx.y;

    int wm = (wid & 1) * 64;
    int wn = (wid >> 1) * 32;
    int arow = wm + (lane & 15);
    int akb  = (lane >> 4) * 16;
    int brow = wn + (lane & 7);
    int bkb  = ((lane >> 3) & 1) * 16;

    float acc[4][4][4];
    #pragma unroll
    for (int mi = 0; mi < 4; ++mi)
        #pragma unroll
        for (int ni = 0; ni < 4; ++ni)
            #pragma unroll
            for (int q = 0; q < 4; ++q) acc[mi][ni][q] = 0.f;

    #pragma unroll
    for (int s = 0; s < GSTAGES - 1; ++s) {
        issue_stage(sb, s, s, tid, Xh, Wh, by, bx);
        cp_commit();
    }

    for (int it = 0; it < 32; ++it) {
        cp_wait<GSTAGES - 2>();
        __syncthreads();

        int nxt = it + GSTAGES - 1;
        if (nxt < 32) issue_stage(sb, nxt % GSTAGES, nxt, tid, Xh, Wh, by, bx);
        cp_commit();

        uint32_t base = sb + (it % GSTAGES) * STAGE_BYTES;
        #pragma unroll
        for (int ks = 0; ks < 4; ++ks) {
            uint32_t af[4][4], bf[4][2];
            #pragma unroll
            for (int mi = 0; mi < 4; ++mi)
                ldsm_x4(af[mi], base + swz((uint32_t)((arow + mi * 16) * 128 + ks * 32 + akb)));
            #pragma unroll
            for (int ni = 0; ni < 4; ++ni)
                ldsm_x2(bf[ni], base + 16384 + swz((uint32_t)((brow + ni * 8) * 128 + ks * 32 + bkb)));
            #pragma unroll
            for (int mi = 0; mi < 4; ++mi)
                #pragma unroll
                for (int ni = 0; ni < 4; ++ni)
                    mma16816f16(acc[mi][ni], af[mi], bf[ni]);
        }
    }

    int m0 = by * 128 + wm + (lane >> 2);
    int n0 = bx * 128 + wn + (lane & 3) * 2;
    #pragma unroll
    for (int mi = 0; mi < 4; ++mi) {
        #pragma unroll
        for (int ni = 0; ni < 4; ++ni) {
            float* p = out + (size_t)(m0 + mi * 16) * 2048 + n0 + ni * 8;
            *(float2*)p = make_float2(acc[mi][ni][0] * 256.f, acc[mi][ni][1] * 256.f);
            *(float2*)(p + 8 * 2048) = make_float2(acc[mi][ni][2] * 256.f, acc[mi][ni][3] * 256.f);
        }
    }
}

// ---------------- launch ------------------------------------------------------
extern "C" void kernel_launch(void* const* d_in, const int* in_sizes, int n_in,
                              void* d_out, int out_size)
{
    (void)in_sizes; (void)n_in; (void)out_size;
    const float* x = (const float*)d_in[0];
    const float* p[9];
    for (int i = 0; i < 9; ++i) p[i] = (const float*)d_in[1 + i];

    unsigned char *Xh, *Wh;
    cudaGetSymbolAddress((void**)&Xh, g_Xh);
    cudaGetSymbolAddress((void**)&Wh, g_Wh);

    conv_X<<<8192, 256>>>(x, Xh);                                            // 0
    W_all<<<128, 256>>>(p[0], p[1], p[2], p[3], p[4],
                        p[5], p[6], p[7], p[8], Wh);                         // 1
    cudaFuncSetAttribute(tt_gemm_f16, cudaFuncAttributeMaxDynamicSharedMemorySize, GEMM_SMEM);
    tt_gemm_f16<<<dim3(16, 64), 256, GEMM_SMEM>>>(Xh, Wh, (float*)d_out);    // 2
}